// round 15
// baseline (speedup 1.0000x reference)
#include <cuda_runtime.h>

#define IMG_H 512
#define IMG_W 512
#define TX 32
#define HALO 5
#define IN_W 42              // TX + 2*HALO
#define RH 42                // H/sxy row count held in SMEM
#define SP 43                // sxy row stride in float2 slots (conflict-free, verified)
#define HP 33                // Hmap row stride in float4 slots (conflict-free, verified)
#define NT 256
#define TILES 8              // 8 tiles of 32 rows = 256-row half-strip per block

#define C1V 1.0e-4f
#define C2V 9.0e-4f
#define EPSV 1.0e-8f

// Normalized 1D Gaussian, sigma=1.5, window 11 (symmetric). Compile-time
// constants -> FFMA with immediate multiplier (rt_SMSP=1 on sm_10x).
__device__ constexpr float GW[11] = {
    0.00102838f, 0.00759876f, 0.03600077f, 0.10936069f, 0.21300553f,
    0.26601172f,
    0.21300553f, 0.10936069f, 0.03600077f, 0.00759876f, 0.00102838f
};

__global__ void zero_out_kernel(float* out) { out[0] = 0.0f; }

__global__ __launch_bounds__(NT, 5) void ssim_kernel(
    const float* __restrict__ x, const float* __restrict__ y,
    float* __restrict__ out, float inv_n)
{
    // Rolling strip: block covers 32x256 outputs (8 tiles). Hmap is shifted
    // down 32 rows per tile (10 overlap rows copied), so only 32 new H rows
    // are computed per tile instead of 42, and only 32 input rows loaded.
    __shared__ float2 sxy[RH * SP];     // (s, d) new input rows     14.4 KB
    __shared__ float4 Hmap[RH * HP];    // (Hs, Hd, Hss, Hdd)       22.2 KB
    __shared__ float  red[8];

    const int tid = threadIdx.x;
    const int x0 = blockIdx.x * TX - HALO;
    const int ybase = blockIdx.y * (TILES * 32);
    const size_t imgoff = (size_t)blockIdx.z * (IMG_H * IMG_W);
    const float* xb = x + imgoff;
    const float* yb = y + imgoff;

    const bool xok = (x0 >= 0) & (x0 + IN_W <= IMG_W);
    const int p1r0 = tid / IN_W;        // phase-1 walker start (one div total)
    const int p1c0 = tid - p1r0 * IN_W;

    float lsum = 0.0f;

    for (int t = 0; t < TILES; t++) {
        const int oy0 = ybase + 32 * t;          // first output row of tile

        // ---- Shift Hmap down 32 rows: rows 0..9 <- rows 32..41 ----
        // (src 32..41 and dst 0..9 disjoint; prev-iter sync ordered P3 reads)
        if (t > 0) {
            const int cc = tid & 31;
            const int r  = tid >> 5;             // 0..7
            Hmap[r * HP + cc] = Hmap[(r + 32) * HP + cc];
            if (tid < 64) {
                const int r2 = 8 + (tid >> 5);   // 8..9
                Hmap[r2 * HP + cc] = Hmap[(r2 + 32) * HP + cc];
            }
        }

        // ---- Phase 1: load new input rows, coalesced walker ----
        // t=0: 42 rows (gr = ybase-5+r -> sxy row r)
        // t>0: 32 rows (gr = oy0+5+r   -> sxy row r)
        const int rows   = (t == 0) ? RH : 32;
        const int grbase = (t == 0) ? (ybase - HALO) : (oy0 + HALO);
        const bool fast  = xok & (grbase >= 0) & (grbase + rows <= IMG_H);
        {
            int r = p1r0, c = p1c0;
            if (fast) {
                #pragma unroll
                for (int it = 0; it < 7; it++) {
                    if (r < rows) {
                        int g = (grbase + r) * IMG_W + (x0 + c);
                        float xv = __ldg(xb + g);
                        float yv = __ldg(yb + g);
                        sxy[r * SP + c] = make_float2(xv + yv, xv - yv);
                    }
                    c += 4; r += 6;
                    if (c >= IN_W) { c -= IN_W; r += 1; }
                }
            } else {
                #pragma unroll
                for (int it = 0; it < 7; it++) {
                    if (r < rows) {
                        int gy = grbase + r, gx = x0 + c;
                        float sv = 0.0f, dv = 0.0f;
                        if (gy >= 0 && gy < IMG_H && gx >= 0 && gx < IMG_W) {
                            int g = gy * IMG_W + gx;
                            float xv = __ldg(xb + g);
                            float yv = __ldg(yb + g);
                            sv = xv + yv;
                            dv = xv - yv;
                        }
                        sxy[r * SP + c] = make_float2(sv, dv);
                    }
                    c += 4; r += 6;
                    if (c >= IN_W) { c -= IN_W; r += 1; }
                }
            }
        }
        __syncthreads();

        // ---- Phase 2: horizontal pass, 4-col units ----
        // t=0: 336 units (42 rows x 8 cgs), grid-stride.
        // t>0: 256 units (32 rows x 8 cgs) -> perfect balance, H rows 10..41.
        if (t == 0) {
            for (int u = tid; u < RH * 8; u += NT) {
                const int cg = u / RH;
                const int ln = u - cg * RH;
                const float2* pin = sxy + ln * SP + cg * 4;
                float as[4], ad[4], as2[4], ad2[4];
                #pragma unroll
                for (int i = 0; i < 14; i++) {
                    float2 v = pin[i];
                    float ss = v.x * v.x, dd = v.y * v.y;
                    #pragma unroll
                    for (int k = 0; k < 4; k++) {
                        const int d = i - k;
                        if (d == 0) {
                            as[k]  = v.x * GW[0];
                            ad[k]  = v.y * GW[0];
                            as2[k] = ss  * GW[0];
                            ad2[k] = dd  * GW[0];
                        } else if (d > 0 && d <= 10) {
                            const float w = GW[d];
                            as[k]  = fmaf(v.x, w, as[k]);
                            ad[k]  = fmaf(v.y, w, ad[k]);
                            as2[k] = fmaf(ss,  w, as2[k]);
                            ad2[k] = fmaf(dd,  w, ad2[k]);
                        }
                    }
                }
                const int hb = ln * HP + cg * 4;
                #pragma unroll
                for (int k = 0; k < 4; k++)
                    Hmap[hb + k] = make_float4(as[k], ad[k], as2[k], ad2[k]);
            }
        } else {
            const int cg = tid >> 5;             // 0..7
            const int ln = tid & 31;             // 0..31 (warp covers rows)
            const float2* pin = sxy + ln * SP + cg * 4;
            float as[4], ad[4], as2[4], ad2[4];
            #pragma unroll
            for (int i = 0; i < 14; i++) {
                float2 v = pin[i];
                float ss = v.x * v.x, dd = v.y * v.y;
                #pragma unroll
                for (int k = 0; k < 4; k++) {
                    const int d = i - k;
                    if (d == 0) {
                        as[k]  = v.x * GW[0];
                        ad[k]  = v.y * GW[0];
                        as2[k] = ss  * GW[0];
                        ad2[k] = dd  * GW[0];
                    } else if (d > 0 && d <= 10) {
                        const float w = GW[d];
                        as[k]  = fmaf(v.x, w, as[k]);
                        ad[k]  = fmaf(v.y, w, ad[k]);
                        as2[k] = fmaf(ss,  w, as2[k]);
                        ad2[k] = fmaf(dd,  w, ad2[k]);
                    }
                }
            }
            const int hb = (10 + ln) * HP + cg * 4;
            #pragma unroll
            for (int k = 0; k < 4; k++)
                Hmap[hb + k] = make_float4(as[k], ad[k], as2[k], ad2[k]);
        }
        __syncthreads();

        // ---- Phase 3: vertical pass + SSIM (identical to champion) ----
        {
            const int c     = tid & 31;
            const int rbase = (tid >> 5) * 4;
            float ms[4], md[4], mss[4], mdd[4];
            const float4* p = Hmap + rbase * HP + c;
            #pragma unroll
            for (int j = 0; j < 14; j++) {
                float4 h = p[j * HP];
                #pragma unroll
                for (int k = 0; k < 4; k++) {
                    const int d = j - k;
                    if (d == 0) {
                        ms[k]  = h.x * GW[0];
                        md[k]  = h.y * GW[0];
                        mss[k] = h.z * GW[0];
                        mdd[k] = h.w * GW[0];
                    } else if (d > 0 && d <= 10) {
                        const float w = GW[d];
                        ms[k]  = fmaf(h.x, w, ms[k]);
                        md[k]  = fmaf(h.y, w, md[k]);
                        mss[k] = fmaf(h.z, w, mss[k]);
                        mdd[k] = fmaf(h.w, w, mdd[k]);
                    }
                }
            }
            #pragma unroll
            for (int k = 0; k < 4; k++) {
                float mus = ms[k],  mud = md[k];
                float a = fmaf(mus, mus, -(mud * mud));
                float b = fmaf(mus, mus,  (mud * mud));
                float e = mss[k] - mdd[k];
                float f = mss[k] + mdd[k];
                float n   = fmaf(0.5f, a, C1V) * fmaf(0.5f, e - a, C2V);
                float den = fmaf(0.5f, b, C1V) * fmaf(0.5f, f - b, C2V) + EPSV;
                float v = fmaf(__fdividef(n, den), 0.5f, 0.5f);
                v = fminf(fmaxf(v, 0.0f), 1.0f);
                lsum += v;
            }
        }
        __syncthreads();   // protect Hmap rows read by P3 from next shift/P2
    }

    // ---- Reduction: warp shuffle -> smem -> block -> atomic ----
    #pragma unroll
    for (int off = 16; off > 0; off >>= 1)
        lsum += __shfl_xor_sync(0xFFFFFFFFu, lsum, off);
    if ((tid & 31) == 0) red[tid >> 5] = lsum;
    __syncthreads();
    if (tid == 0) {
        float tsum = 0.0f;
        #pragma unroll
        for (int w = 0; w < 8; w++) tsum += red[w];
        atomicAdd(out, tsum * inv_n);
    }
}

extern "C" void kernel_launch(void* const* d_in, const int* in_sizes, int n_in,
                              void* d_out, int out_size)
{
    const float* x = (const float*)d_in[0];
    const float* y = (const float*)d_in[1];
    float* out = (float*)d_out;

    zero_out_kernel<<<1, 1>>>(out);

    dim3 grid(IMG_W / TX, IMG_H / (TILES * 32), 16 * 3);   // 16 x 2 x 48
    const float inv_n = 1.0f / (float)(16 * 3 * IMG_H * IMG_W);
    ssim_kernel<<<grid, NT>>>(x, y, out, inv_n);
}

// round 17
// speedup vs baseline: 1.0039x; 1.0039x over previous
#include <cuda_runtime.h>

#define IMG_H 512
#define IMG_W 512
#define TX 32
#define TY 32
#define HALO 5
#define IN_H 42              // TY + 2*HALO rows
#define NCP 22               // col-pairs per row (44 cols: logical -1..42)
#define SP2 45               // sxy row stride in float2 slots (45: odd, P2 LDS conflict-free)
#define HP 33                // Hmap row stride in float4 slots (verified conflict-free)
#define NT 256

#define C1V 1.0e-4f
#define C2V 9.0e-4f
#define EPSV 1.0e-8f

// Normalized 1D Gaussian, sigma=1.5, window 11 (symmetric). Compile-time
// constants -> FFMA with immediate multiplier (rt_SMSP=1 on sm_10x).
__device__ constexpr float GW[11] = {
    0.00102838f, 0.00759876f, 0.03600077f, 0.10936069f, 0.21300553f,
    0.26601172f,
    0.21300553f, 0.10936069f, 0.03600077f, 0.00759876f, 0.00102838f
};

__global__ void zero_out_kernel(float* out) { out[0] = 0.0f; }

__global__ __launch_bounds__(NT, 5) void ssim_kernel(
    const float* __restrict__ x, const float* __restrict__ y,
    float* __restrict__ out, float inv_n)
{
    // Sum/difference transform: convolve s=x+y, d=x-y -> 4 maps.
    // sxy slot c holds logical halo col c-1 (halo widened 1 col left so the
    // global base col x0c = 32*bx-6 is EVEN -> aligned float2 LDG.64).
    __shared__ float2 sxy[IN_H * SP2];   // (s, d)               15.1 KB
    __shared__ float4 Hmap[IN_H * HP];   // (Hs, Hd, Hss, Hdd)   22.2 KB
    __shared__ float  red[8];

    const int tid = threadIdx.x;
    const int x0c = blockIdx.x * TX - (HALO + 1);   // even
    const int y0  = blockIdx.y * TY - HALO;
    const size_t imgoff = (size_t)blockIdx.z * (IMG_H * IMG_W);
    const float* xb = x + imgoff;
    const float* yb = y + imgoff;

    // ---- Phase 1: vectorized pair loads. 924 units (42 rows x 22 pairs),
    // 4 iterations over 256 threads. Walker: +256 = +11 rows +14 pairs.
    const bool fast = (x0c >= 0) & (x0c + 2 * NCP <= IMG_W) &
                      (y0 >= 0) & (y0 + IN_H <= IMG_H);
    {
        int r  = tid / NCP;              // one division total
        int pc = tid - r * NCP;
        if (fast) {
            #pragma unroll
            for (int it = 0; it < 4; it++) {
                if (r < IN_H) {          // == (unit < 924)
                    int g = (y0 + r) * IMG_W + (x0c + 2 * pc);
                    float2 xv = *(const float2*)(xb + g);   // aligned: x0c even
                    float2 yv = *(const float2*)(yb + g);
                    sxy[r * SP2 + 2 * pc]     = make_float2(xv.x + yv.x, xv.x - yv.x);
                    sxy[r * SP2 + 2 * pc + 1] = make_float2(xv.y + yv.y, xv.y - yv.y);
                }
                pc += 14; r += 11;
                if (pc >= NCP) { pc -= NCP; r += 1; }
            }
        } else {
            #pragma unroll
            for (int it = 0; it < 4; it++) {
                if (r < IN_H) {
                    int gy = y0 + r;
                    int gx0 = x0c + 2 * pc;
                    const bool rowok = (gy >= 0) & (gy < IMG_H);
                    float s0 = 0.f, d0 = 0.f, s1 = 0.f, d1 = 0.f;
                    if (rowok && gx0 >= 0 && gx0 < IMG_W) {
                        float xv = __ldg(xb + gy * IMG_W + gx0);
                        float yv = __ldg(yb + gy * IMG_W + gx0);
                        s0 = xv + yv; d0 = xv - yv;
                    }
                    if (rowok && gx0 + 1 >= 0 && gx0 + 1 < IMG_W) {
                        float xv = __ldg(xb + gy * IMG_W + gx0 + 1);
                        float yv = __ldg(yb + gy * IMG_W + gx0 + 1);
                        s1 = xv + yv; d1 = xv - yv;
                    }
                    sxy[r * SP2 + 2 * pc]     = make_float2(s0, d0);
                    sxy[r * SP2 + 2 * pc + 1] = make_float2(s1, d1);
                }
                pc += 14; r += 11;
                if (pc >= NCP) { pc -= NCP; r += 1; }
            }
        }
    }
    __syncthreads();

    // ---- Phase 2: horizontal pass, FUSED (single load stream, 4 maps) ----
    // 168 units of 8 output cols; logical col c lives at slot c+1.
    // LDS.64 bank audit (lanes = consecutive rows, stride 45 float2):
    // banks 2*(45r) mod 32 = 2*(13r mod 16): 13 odd -> 16 distinct pairs ✓.
    if (tid < IN_H * 4) {
        const int cg  = tid / IN_H;          // 0..3 (8-col groups)
        const int row = tid - cg * IN_H;     // 0..41
        const float2* pin = sxy + row * SP2 + cg * 8 + 1;
        float as[8], ad[8], as2[8], ad2[8];
        #pragma unroll
        for (int i = 0; i < 18; i++) {
            float2 v = pin[i];
            float ss = v.x * v.x;
            float dd = v.y * v.y;
            #pragma unroll
            for (int k = 0; k < 8; k++) {
                const int d = i - k;
                if (d == 0) {                 // first tap: mul-init (no MOV 0)
                    as[k]  = v.x * GW[0];
                    ad[k]  = v.y * GW[0];
                    as2[k] = ss  * GW[0];
                    ad2[k] = dd  * GW[0];
                } else if (d > 0 && d <= 10) {
                    const float w = GW[d];
                    as[k]  = fmaf(v.x, w, as[k]);
                    ad[k]  = fmaf(v.y, w, ad[k]);
                    as2[k] = fmaf(ss,  w, as2[k]);
                    ad2[k] = fmaf(dd,  w, ad2[k]);
                }
            }
        }
        const int hb = row * HP + cg * 8;
        #pragma unroll
        for (int k = 0; k < 8; k++)
            Hmap[hb + k] = make_float4(as[k], ad[k], as2[k], ad2[k]);
    }
    __syncthreads();

    // ---- Phase 3: vertical pass + SSIM, 4 rows per thread ----
    // LDS.128 bank audit: lane c -> word 4c, conflict-free per wavefront.
    const int c     = tid & 31;
    const int rbase = (tid >> 5) * 4;
    float ms[4], md[4], mss[4], mdd[4];
    const float4* p = Hmap + rbase * HP + c;
    #pragma unroll
    for (int j = 0; j < 14; j++) {
        float4 h = p[j * HP];
        #pragma unroll
        for (int k = 0; k < 4; k++) {
            const int d = j - k;
            if (d == 0) {
                ms[k]  = h.x * GW[0];
                md[k]  = h.y * GW[0];
                mss[k] = h.z * GW[0];
                mdd[k] = h.w * GW[0];
            } else if (d > 0 && d <= 10) {
                const float w = GW[d];
                ms[k]  = fmaf(h.x, w, ms[k]);
                md[k]  = fmaf(h.y, w, md[k]);
                mss[k] = fmaf(h.z, w, mss[k]);
                mdd[k] = fmaf(h.w, w, mdd[k]);
            }
        }
    }

    // SSIM in sum/diff-native form:
    //   a = mus^2-mud^2 (=4 mux*muy)      b = mus^2+mud^2 (=2(mux^2+muy^2))
    //   e = Ess-Edd     (=4 E[xy])        f = Ess+Edd     (=2(E[x^2]+E[y^2]))
    float lsum = 0.0f;
    #pragma unroll
    for (int k = 0; k < 4; k++) {
        float mus = ms[k],  mud = md[k];
        float a = fmaf(mus, mus, -(mud * mud));
        float b = fmaf(mus, mus,  (mud * mud));
        float e = mss[k] - mdd[k];
        float f = mss[k] + mdd[k];
        float n   = fmaf(0.5f, a, C1V) * fmaf(0.5f, e - a, C2V);
        float den = fmaf(0.5f, b, C1V) * fmaf(0.5f, f - b, C2V) + EPSV;
        float v = fmaf(__fdividef(n, den), 0.5f, 0.5f);
        v = fminf(fmaxf(v, 0.0f), 1.0f);
        lsum += v;
    }

    // ---- Reduction: warp shuffle -> smem -> block -> atomic ----
    #pragma unroll
    for (int off = 16; off > 0; off >>= 1)
        lsum += __shfl_xor_sync(0xFFFFFFFFu, lsum, off);
    if ((tid & 31) == 0) red[tid >> 5] = lsum;
    __syncthreads();
    if (tid == 0) {
        float t = 0.0f;
        #pragma unroll
        for (int w = 0; w < 8; w++) t += red[w];
        atomicAdd(out, t * inv_n);
    }
}

extern "C" void kernel_launch(void* const* d_in, const int* in_sizes, int n_in,
                              void* d_out, int out_size)
{
    const float* x = (const float*)d_in[0];
    const float* y = (const float*)d_in[1];
    float* out = (float*)d_out;

    zero_out_kernel<<<1, 1>>>(out);

    dim3 grid(IMG_W / TX, IMG_H / TY, 16 * 3);   // 16 x 16 x 48
    const float inv_n = 1.0f / (float)(16 * 3 * IMG_H * IMG_W);
    ssim_kernel<<<grid, NT>>>(x, y, out, inv_n);
}